// round 5
// baseline (speedup 1.0000x reference)
#include <cuda_runtime.h>
#include <cstdint>

#define CH    256
#define FF    512
#define NB    2048
#define BATCH 8
#define BN_COUNT 16384.0f
#define GRID_TOTAL 128u     // fused kernel CTA count (8*2*8), 1 per SM

#define MT 128
#define NT 256
#define KC 32
#define A_STRIDE 260        // floats per A row (bank-bijective: 4r+t)
#define B_STRIDE 264        // floats per B row (bank-bijective: 8t+r)

#define A_FL       (128 * A_STRIDE)         // 33280
#define B_BUF_FL   (KC * B_STRIDE)          // 8448
#define OFF_A      0
#define OFF_B      A_FL
#define OFF_RED    (A_FL + 2 * B_BUF_FL)    // 50176
#define SMEM_FL    (OFF_RED + 256)          // 50432
#define SMEM_BYTES (SMEM_FL * 4)            // 201728

// Scratch globals (no allocations allowed)
__device__ float    g_Weff[CH*CH];
__device__ float    g_sum[CH];
__device__ float    g_sumsq[CH];
__device__ unsigned g_bar;

__device__ __forceinline__ uint32_t smem_u32(const void* p) {
    uint32_t a;
    asm("{ .reg .u64 t; cvta.to.shared.u64 t, %1; cvt.u32.u64 %0, t; }" : "=r"(a) : "l"(p));
    return a;
}
__device__ __forceinline__ void cp_async16(uint32_t dst, const void* src) {
    asm volatile("cp.async.cg.shared.global [%0], [%1], 16;" :: "r"(dst), "l"(src));
}
__device__ __forceinline__ void cp_commit() {
    asm volatile("cp.async.commit_group;");
}
__device__ __forceinline__ void mma_tf32(float* d, const uint32_t* a, const uint32_t* b) {
    asm volatile(
        "mma.sync.aligned.m16n8k8.row.col.f32.tf32.tf32.f32 "
        "{%0,%1,%2,%3}, {%4,%5,%6,%7}, {%8,%9}, {%0,%1,%2,%3};"
        : "+f"(d[0]), "+f"(d[1]), "+f"(d[2]), "+f"(d[3])
        : "r"(a[0]), "r"(a[1]), "r"(a[2]), "r"(a[3]), "r"(b[0]), "r"(b[1]));
}

// ---------------------------------------------------------------------------
// Kernel 0: zero g_Weff + BN accumulators + barrier counter.
// ---------------------------------------------------------------------------
__global__ void zero_kernel() {
    int i = blockIdx.x * 256 + threadIdx.x;        // 16384 float4 slots
    ((float4*)g_Weff)[i] = make_float4(0.f, 0.f, 0.f, 0.f);
    if (blockIdx.x == 0) {
        g_sum[threadIdx.x]   = 0.f;
        g_sumsq[threadIdx.x] = 0.f;
        if (threadIdx.x == 0) g_bar = 0u;
    }
}

// ---------------------------------------------------------------------------
// Kernel A: W_eff += Wout @ Wv  (256x512 @ 512x256), split-K SIMT.
// grid (4,4,4) = (c-tile, o-tile, k-slice). 256 threads, 4x4 regs/thread.
// ---------------------------------------------------------------------------
__global__ void __launch_bounds__(256, 4)
weff_kernel(const float* __restrict__ Wout,
            const float* __restrict__ Wv) {
    __shared__ float Ws[64][33];
    __shared__ float Vs[32][68];

    int tid = threadIdx.x;
    int to  = tid >> 4;
    int tc  = tid & 15;
    int c0  = blockIdx.x * 64;
    int o0  = blockIdx.y * 64;
    int k0  = blockIdx.z * 128;

    float acc[4][4];
    #pragma unroll
    for (int i = 0; i < 4; i++)
        #pragma unroll
        for (int j = 0; j < 4; j++) acc[i][j] = 0.f;

    for (int kc = 0; kc < 4; kc++) {
        int kb = k0 + kc * 32;
        #pragma unroll
        for (int it = 0; it < 8; it++) {
            int idx = tid + it * 256;
            int r = idx >> 5, kk = idx & 31;
            Ws[r][kk] = Wout[(o0 + r) * FF + kb + kk];
        }
        #pragma unroll
        for (int it = 0; it < 8; it++) {
            int idx = tid + it * 256;
            int kk = idx >> 6, cc = idx & 63;
            Vs[kk][cc] = Wv[(size_t)(kb + kk) * CH + c0 + cc];
        }
        __syncthreads();
        #pragma unroll
        for (int kk = 0; kk < 32; kk++) {
            float4 b = *(const float4*)&Vs[kk][tc * 4];
            float bv[4] = {b.x, b.y, b.z, b.w};
            #pragma unroll
            for (int i = 0; i < 4; i++) {
                float a = Ws[to * 4 + i][kk];
                #pragma unroll
                for (int j = 0; j < 4; j++)
                    acc[i][j] += a * bv[j];
            }
        }
        __syncthreads();
    }
    #pragma unroll
    for (int i = 0; i < 4; i++)
        #pragma unroll
        for (int j = 0; j < 4; j++)
            atomicAdd(&g_Weff[(o0 + to * 4 + i) * CH + c0 + tc * 4 + j], acc[i][j]);
}

// ---------------------------------------------------------------------------
// Kernel B: tf32 mma GEMM (A resident in smem) + stats + grid barrier + norm.
// Per CTA: O[128,256] = W_eff[mBase:+128, :256] @ x_b[:, n0:n0+256]
// grid (8, 2, 8) = 128 CTAs, exactly 1 per SM. 256 threads, 8 warps.
// Warp tile 32(m) x 128(n): 2 x 16 mma.m16n8k8.
// ---------------------------------------------------------------------------
__global__ void __launch_bounds__(256, 1)
fused_kernel(const float* __restrict__ x,
             const float* __restrict__ bout,
             const float* __restrict__ gamma,
             const float* __restrict__ beta,
             float* __restrict__ out) {
    extern __shared__ float smf[];
    uint32_t smb = smem_u32(smf);

    int tid  = threadIdx.x;
    int wid  = tid >> 5;
    int lane = tid & 31;
    int r    = lane >> 2;        // groupID 0..7
    int t    = lane & 3;         // threadInGroup 0..3
    int wRow = wid & 3;          // m offset *32
    int wCol = wid >> 2;         // n offset *128

    int n0    = blockIdx.x * NT;
    int mBase = blockIdx.y * MT;
    int b     = blockIdx.z;
    const float* xb = x   + (size_t)b * CH * NB;
    float*       ob = out + (size_t)b * CH * NB;

    smf[OFF_RED + tid] = 0.f;

    float acc[2][16][4];
    #pragma unroll
    for (int mt = 0; mt < 2; mt++)
        #pragma unroll
        for (int nt = 0; nt < 16; nt++)
            #pragma unroll
            for (int q = 0; q < 4; q++) acc[mt][nt][q] = 0.f;

    // ---- A resident load: W_eff[mBase:+128, 0:256] -> smem (group 0) ----
    #pragma unroll
    for (int it = 0; it < 32; it++) {
        int e = tid + it * 256;          // 0..8191 float4 slots
        int m = e >> 6, c4 = e & 63;
        cp_async16(smb + (OFF_A + m * A_STRIDE + c4 * 4) * 4,
                   &g_Weff[(mBase + m) * CH + c4 * 4]);
    }
    cp_commit();

    // ---- B chunk loader ----
    #define LOAD_B(buf, k0)                                                    \
    {                                                                          \
        uint32_t bdst = smb + (OFF_B + (buf) * B_BUF_FL) * 4;                  \
        _Pragma("unroll")                                                      \
        for (int it = 0; it < 8; it++) {                                       \
            int e = tid + it * 256;      /* 0..2047 float4 slots */            \
            int k = e >> 6, n4 = e & 63;                                       \
            cp_async16(bdst + (k * B_STRIDE + n4 * 4) * 4,                     \
                       &xb[(size_t)((k0) + k) * NB + n0 + n4 * 4]);            \
        }                                                                      \
    }

    LOAD_B(0, 0);
    cp_commit();

    const uint32_t* Au = (const uint32_t*)(smf + OFF_A);

    for (int i = 0; i < 8; i++) {
        int buf = i & 1;
        if (i < 7) {
            LOAD_B((i + 1) & 1, (i + 1) * KC);
            cp_commit();
            asm volatile("cp.async.wait_group 1;");
        } else {
            asm volatile("cp.async.wait_group 0;");
        }
        __syncthreads();

        const uint32_t* Bu = (const uint32_t*)(smf + OFF_B + buf * B_BUF_FL);

        #pragma unroll
        for (int kc = 0; kc < 4; kc++) {
            int k8  = i * KC + kc * 8;   // A global-k
            int bk8 = kc * 8;            // B local-k
            uint32_t afr[2][4];
            #pragma unroll
            for (int mt = 0; mt < 2; mt++) {
                int m = wRow * 32 + mt * 16 + r;
                afr[mt][0] = Au[m * A_STRIDE + k8 + t];
                afr[mt][1] = Au[(m + 8) * A_STRIDE + k8 + t];
                afr[mt][2] = Au[m * A_STRIDE + k8 + t + 4];
                afr[mt][3] = Au[(m + 8) * A_STRIDE + k8 + t + 4];
            }
            #pragma unroll
            for (int nt = 0; nt < 16; nt++) {
                int n = wCol * 128 + nt * 8 + r;
                uint32_t bfr[2];
                bfr[0] = Bu[(bk8 + t) * B_STRIDE + n];
                bfr[1] = Bu[(bk8 + t + 4) * B_STRIDE + n];
                mma_tf32(acc[0][nt], afr[0], bfr);
                mma_tf32(acc[1][nt], afr[1], bfr);
            }
        }
        __syncthreads();
    }

    // ---------------- epilogue 1: stats only ----------------
    float* s_red = smf + OFF_RED;
    #pragma unroll
    for (int mt = 0; mt < 2; mt++) {
        #pragma unroll
        for (int rv = 0; rv < 2; rv++) {
            int rl = wRow * 32 + mt * 16 + rv * 8 + r;
            int rg = mBase + rl;
            float bo = bout[rg];
            float ps = 0.f, pq = 0.f;
            #pragma unroll
            for (int nt = 0; nt < 16; nt++) {
                int col = n0 + wCol * 128 + nt * 8 + t * 2;
                size_t gi = (size_t)rg * NB + col;
                float2 xv = *(const float2*)&xb[gi];
                float y0 = xv.x + fmaxf(acc[mt][nt][rv * 2 + 0] + bo, 0.f);
                float y1 = xv.y + fmaxf(acc[mt][nt][rv * 2 + 1] + bo, 0.f);
                ps += y0 + y1;
                pq += y0 * y0 + y1 * y1;
            }
            atomicAdd(&s_red[rl], ps);
            atomicAdd(&s_red[128 + rl], pq);
        }
    }
    __syncthreads();
    if (tid < 128) {
        atomicAdd(&g_sum[mBase + tid],   s_red[tid]);
        atomicAdd(&g_sumsq[mBase + tid], s_red[128 + tid]);
    }
    __threadfence();
    __syncthreads();

    // ---------------- grid-wide barrier (128 CTAs, 1/SM) ----------------
    if (tid == 0) {
        atomicAdd(&g_bar, 1u);
        unsigned v;
        do {
            asm volatile("ld.acquire.gpu.u32 %0, [%1];" : "=r"(v) : "l"(&g_bar));
        } while (v < GRID_TOTAL);
    }
    __syncthreads();

    // ---------------- epilogue 2: normalize + single store ----------------
    #pragma unroll
    for (int mt = 0; mt < 2; mt++) {
        #pragma unroll
        for (int rv = 0; rv < 2; rv++) {
            int rl = wRow * 32 + mt * 16 + rv * 8 + r;
            int rg = mBase + rl;
            float bo = bout[rg];
            float m  = __ldcg(&g_sum[rg])   * (1.0f / BN_COUNT);
            float vv = __ldcg(&g_sumsq[rg]) * (1.0f / BN_COUNT) - m * m;
            float sc = gamma[rg] * rsqrtf(vv + 1e-5f);
            float bi = beta[rg] - m * sc;
            #pragma unroll
            for (int nt = 0; nt < 16; nt++) {
                int col = n0 + wCol * 128 + nt * 8 + t * 2;
                size_t gi = (size_t)rg * NB + col;
                float2 xv = *(const float2*)&xb[gi];
                float y0 = xv.x + fmaxf(acc[mt][nt][rv * 2 + 0] + bo, 0.f);
                float y1 = xv.y + fmaxf(acc[mt][nt][rv * 2 + 1] + bo, 0.f);
                *(float2*)&ob[gi] = make_float2(y0 * sc + bi, y1 * sc + bi);
            }
        }
    }
}

// ---------------------------------------------------------------------------
extern "C" void kernel_launch(void* const* d_in, const int* in_sizes, int n_in,
                              void* d_out, int out_size) {
    const float* x     = (const float*)d_in[0];
    // d_in[1]=Wk, d_in[2]=Wq unused (softmax row-sums == 1)
    const float* Wv    = (const float*)d_in[3];
    const float* Wout  = (const float*)d_in[4];
    const float* bout  = (const float*)d_in[5];
    const float* gamma = (const float*)d_in[6];
    const float* beta  = (const float*)d_in[7];
    float* out = (float*)d_out;

    cudaFuncSetAttribute(fused_kernel,
                         cudaFuncAttributeMaxDynamicSharedMemorySize, SMEM_BYTES);

    zero_kernel<<<64, 256>>>();
    weff_kernel<<<dim3(4, 4, 4), 256>>>(Wout, Wv);
    fused_kernel<<<dim3(NB / NT, CH / MT, BATCH), 256, SMEM_BYTES>>>(
        x, bout, gamma, beta, out);
}

// round 7
// speedup vs baseline: 1.0611x; 1.0611x over previous
#include <cuda_runtime.h>
#include <cstdint>

#define CH    256
#define FF    512
#define NB    2048
#define BATCH 8
#define BN_COUNT 16384.0f
#define NCTAS 128u

#define MT 128
#define NT 256
#define KC 32
#define A_STRIDE 260        // floats per A row (bank map 4r+t: bijective)
#define B_STRIDE 264        // floats per B row (bank map 8t+r: bijective)

#define A_FL       (128 * A_STRIDE)         // 33280 floats
#define B_BUF_FL   (KC * B_STRIDE)          // 8448 floats
#define OFF_A      0
#define OFF_B      A_FL
#define OFF_RED    (A_FL + 2 * B_BUF_FL)    // 50176
#define SMEM_FL    (OFF_RED + 256)
#define SMEM_BYTES (SMEM_FL * 4)            // 201728 B

// Scratch globals (module-load zeroed; we never need re-zeroing)
__device__ float    g_Weff[CH * CH];
__device__ float    g_part [128 * 128];   // per-CTA per-channel sum
__device__ float    g_partq[128 * 128];   // per-CTA per-channel sumsq
__device__ unsigned g_bar;                // monotonic ticket counter

__device__ __forceinline__ uint32_t smem_u32(const void* p) {
    uint32_t a;
    asm("{ .reg .u64 t; cvta.to.shared.u64 t, %1; cvt.u32.u64 %0, t; }" : "=r"(a) : "l"(p));
    return a;
}
__device__ __forceinline__ void cp_async16(uint32_t dst, const void* src) {
    asm volatile("cp.async.cg.shared.global [%0], [%1], 16;" :: "r"(dst), "l"(src));
}
__device__ __forceinline__ void cp_commit() {
    asm volatile("cp.async.commit_group;");
}
__device__ __forceinline__ void mma_tf32(float* d, const uint32_t* a, const uint32_t* b) {
    asm volatile(
        "mma.sync.aligned.m16n8k8.row.col.f32.tf32.tf32.f32 "
        "{%0,%1,%2,%3}, {%4,%5,%6,%7}, {%8,%9}, {%0,%1,%2,%3};"
        : "+f"(d[0]), "+f"(d[1]), "+f"(d[2]), "+f"(d[3])
        : "r"(a[0]), "r"(a[1]), "r"(a[2]), "r"(a[3]), "r"(b[0]), "r"(b[1]));
}

// Monotonic grid barrier: no reset, generation from ticket value.
__device__ __forceinline__ void grid_barrier(int tid) {
    __syncthreads();
    if (tid == 0) {
        __threadfence();
        unsigned tck = atomicAdd(&g_bar, 1u);
        unsigned target = (tck & ~(NCTAS - 1u)) + NCTAS;
        unsigned v;
        do {
            asm volatile("ld.acquire.gpu.u32 %0, [%1];" : "=r"(v) : "l"(&g_bar));
        } while ((int)(v - target) < 0);
    }
    __syncthreads();
}

// ---------------------------------------------------------------------------
// THE kernel. grid 128 (1/SM), 512 threads (16 warps).
// Phase 0: W_eff slice compute. Barrier. GEMM mainloop (tf32 mma).
// Epilogue 1: per-CTA BN partials. Barrier. Reduce. Epilogue 2: norm + store.
// ---------------------------------------------------------------------------
__global__ void __launch_bounds__(512, 1)
mega_kernel(const float* __restrict__ x,
            const float* __restrict__ Wv,
            const float* __restrict__ Wout,
            const float* __restrict__ bout,
            const float* __restrict__ gamma,
            const float* __restrict__ beta,
            float* __restrict__ out) {
    extern __shared__ float smf[];
    uint32_t smb = smem_u32(smf);

    int tid  = threadIdx.x;
    int bid  = blockIdx.x;
    int wid  = tid >> 5;
    int lane = tid & 31;
    int r    = lane >> 2;          // groupID 0..7
    int t    = lane & 3;           // 0..3
    int wRow = wid & 3;            // m * 32
    int wCol = wid >> 2;           // n * 64  (0..3)

    // GEMM tile mapping
    int xt    = bid & 7;                 // n-tile
    int yt    = (bid >> 3) & 1;          // m-tile
    int zt    = bid >> 4;                // batch
    int n0    = xt * NT;
    int mBase = yt * MT;
    const float* xb = x   + (size_t)zt * CH * NB;
    float*       ob = out + (size_t)zt * CH * NB;

    // ---- prefetch first B chunk (independent of W_eff) ----
    #define LOAD_B(buf, k0)                                                    \
    {                                                                          \
        uint32_t bdst = smb + (OFF_B + (buf) * B_BUF_FL) * 4;                  \
        _Pragma("unroll")                                                      \
        for (int it = 0; it < 4; it++) {                                       \
            int e = tid + it * 512;      /* 0..2047 float4 slots */            \
            int k = e >> 6, n4 = e & 63;                                       \
            cp_async16(bdst + (k * B_STRIDE + n4 * 4) * 4,                     \
                       &xb[(size_t)((k0) + k) * NB + n0 + n4 * 4]);            \
        }                                                                      \
    }
    LOAD_B(0, 0);
    cp_commit();                    // group: B0

    // ---- Phase 0: W_eff[o][c] slice, 1 entry per thread ----
    {
        int o = ((bid >> 3) & 15) * 16 + (tid >> 5);   // bid>>3: 0..15
        int c = (bid & 7) * 32 + (tid & 31);
        const float* wr = Wout + (size_t)o * FF;
        float a0 = 0.f, a1 = 0.f, a2 = 0.f, a3 = 0.f;
        #pragma unroll 8
        for (int k = 0; k < FF; k += 4) {
            float4 w = *(const float4*)(wr + k);
            a0 = fmaf(w.x, Wv[(size_t)(k + 0) * CH + c], a0);
            a1 = fmaf(w.y, Wv[(size_t)(k + 1) * CH + c], a1);
            a2 = fmaf(w.z, Wv[(size_t)(k + 2) * CH + c], a2);
            a3 = fmaf(w.w, Wv[(size_t)(k + 3) * CH + c], a3);
        }
        g_Weff[o * CH + c] = (a0 + a1) + (a2 + a3);
    }
    grid_barrier(tid);              // W_eff globally visible

    // ---- A resident load: W_eff[mBase:+128, 0:256] -> smem ----
    #pragma unroll
    for (int it = 0; it < 16; it++) {
        int e = tid + it * 512;          // 0..8191 float4 slots
        int m = e >> 6, c4 = e & 63;
        cp_async16(smb + (OFF_A + m * A_STRIDE + c4 * 4) * 4,
                   &g_Weff[(mBase + m) * CH + c4 * 4]);
    }
    cp_commit();                    // group: A

    if (tid < 256) smf[OFF_RED + tid] = 0.f;

    float acc[2][8][4];
    #pragma unroll
    for (int mt = 0; mt < 2; mt++)
        #pragma unroll
        for (int nt = 0; nt < 8; nt++)
            #pragma unroll
            for (int q = 0; q < 4; q++) acc[mt][nt][q] = 0.f;

    const uint32_t* Au = (const uint32_t*)(smf + OFF_A);

    // ---- mainloop: 8 K-chunks, double-buffered B ----
    for (int i = 0; i < 8; i++) {
        int buf = i & 1;
        if (i < 7) {
            LOAD_B((i + 1) & 1, (i + 1) * KC);
            cp_commit();
            asm volatile("cp.async.wait_group 1;");
        } else {
            asm volatile("cp.async.wait_group 0;");
        }
        __syncthreads();

        const uint32_t* Bu = (const uint32_t*)(smf + OFF_B + buf * B_BUF_FL);

        #pragma unroll
        for (int kc = 0; kc < 4; kc++) {
            int k8  = i * KC + kc * 8;   // A k (global)
            int bk8 = kc * 8;            // B k (chunk-local)
            uint32_t afr[2][4];
            #pragma unroll
            for (int mt = 0; mt < 2; mt++) {
                int m = wRow * 32 + mt * 16 + r;
                afr[mt][0] = Au[m * A_STRIDE + k8 + t];
                afr[mt][1] = Au[(m + 8) * A_STRIDE + k8 + t];
                afr[mt][2] = Au[m * A_STRIDE + k8 + t + 4];
                afr[mt][3] = Au[(m + 8) * A_STRIDE + k8 + t + 4];
            }
            #pragma unroll
            for (int nt = 0; nt < 8; nt++) {
                int n = wCol * 64 + nt * 8 + r;
                uint32_t bfr[2];
                bfr[0] = Bu[(bk8 + t) * B_STRIDE + n];
                bfr[1] = Bu[(bk8 + t + 4) * B_STRIDE + n];
                mma_tf32(acc[0][nt], afr[0], bfr);
                mma_tf32(acc[1][nt], afr[1], bfr);
            }
        }
        __syncthreads();
    }

    // ---- epilogue 1: per-CTA channel partial sums ----
    float* s_red = smf + OFF_RED;
    #pragma unroll
    for (int mt = 0; mt < 2; mt++) {
        #pragma unroll
        for (int rv = 0; rv < 2; rv++) {
            int rl = wRow * 32 + mt * 16 + rv * 8 + r;   // local channel 0..127
            int rg = mBase + rl;
            float bo = bout[rg];
            float ps = 0.f, pq = 0.f;
            #pragma unroll
            for (int nt = 0; nt < 8; nt++) {
                int col = n0 + wCol * 64 + nt * 8 + t * 2;
                size_t gi = (size_t)rg * NB + col;
                float2 xv = *(const float2*)&xb[gi];
                float y0 = xv.x + fmaxf(acc[mt][nt][rv * 2 + 0] + bo, 0.f);
                float y1 = xv.y + fmaxf(acc[mt][nt][rv * 2 + 1] + bo, 0.f);
                ps += y0 + y1;
                pq += y0 * y0 + y1 * y1;
            }
            atomicAdd(&s_red[rl], ps);
            atomicAdd(&s_red[128 + rl], pq);
        }
    }
    __syncthreads();
    if (tid < 128)
        g_part [bid * 128 + tid] = s_red[tid];
    else if (tid < 256)
        g_partq[bid * 128 + (tid - 128)] = s_red[tid];

    grid_barrier(tid);              // all partials visible

    // ---- reduce 64 partials (same m-tile: y==yt) into smem stats ----
    if (tid < 128) {
        float s = 0.f;
        #pragma unroll 8
        for (int j = 0; j < 64; j++) {
            int pid = (j & 7) + 8 * yt + 16 * (j >> 3);   // x + 8y + 16z
            s += g_part[pid * 128 + tid];
        }
        s_red[tid] = s;
    } else if (tid < 256) {
        int ch = tid - 128;
        float s = 0.f;
        #pragma unroll 8
        for (int j = 0; j < 64; j++) {
            int pid = (j & 7) + 8 * yt + 16 * (j >> 3);
            s += g_partq[pid * 128 + ch];
        }
        s_red[tid] = s;
    }
    __syncthreads();

    // ---- epilogue 2: recompute y, normalize, single store ----
    #pragma unroll
    for (int mt = 0; mt < 2; mt++) {
        #pragma unroll
        for (int rv = 0; rv < 2; rv++) {
            int rl = wRow * 32 + mt * 16 + rv * 8 + r;
            int rg = mBase + rl;
            float bo = bout[rg];
            float m  = s_red[rl]       * (1.0f / BN_COUNT);
            float vv = s_red[128 + rl] * (1.0f / BN_COUNT) - m * m;
            float sc = gamma[rg] * rsqrtf(vv + 1e-5f);
            float bi = beta[rg] - m * sc;
            #pragma unroll
            for (int nt = 0; nt < 8; nt++) {
                int col = n0 + wCol * 64 + nt * 8 + t * 2;
                size_t gi = (size_t)rg * NB + col;
                float2 xv = *(const float2*)&xb[gi];
                float y0 = xv.x + fmaxf(acc[mt][nt][rv * 2 + 0] + bo, 0.f);
                float y1 = xv.y + fmaxf(acc[mt][nt][rv * 2 + 1] + bo, 0.f);
                *(float2*)&ob[gi] = make_float2(y0 * sc + bi, y1 * sc + bi);
            }
        }
    }
}

// ---------------------------------------------------------------------------
extern "C" void kernel_launch(void* const* d_in, const int* in_sizes, int n_in,
                              void* d_out, int out_size) {
    const float* x     = (const float*)d_in[0];
    // d_in[1]=Wk, d_in[2]=Wq unused (softmax row-sums == 1 -> agg == V)
    const float* Wv    = (const float*)d_in[3];
    const float* Wout  = (const float*)d_in[4];
    const float* bout  = (const float*)d_in[5];
    const float* gamma = (const float*)d_in[6];
    const float* beta  = (const float*)d_in[7];
    float* out = (float*)d_out;

    cudaFuncSetAttribute(mega_kernel,
                         cudaFuncAttributeMaxDynamicSharedMemorySize, SMEM_BYTES);

    mega_kernel<<<NCTAS, 512, SMEM_BYTES>>>(x, Wv, Wout, bout, gamma, beta, out);
}